// round 6
// baseline (speedup 1.0000x reference)
#include <cuda_runtime.h>
#include <cuda_fp16.h>
#include <cstdint>

#define NN    8192
#define IND   512
#define OUTD  256
#define BM    64
#define BK    64
#define SPLITS 2
#define JRANGE (NN / SPLITS)      // 4096
#define NTILES (JRANGE / BK)      // 64
#define NW32   (NN / 32)          // 256 mask words per row
#define LOG2E 1.4426950408889634f

// ---- dynamic smem: 3 x (64 rows x 512B, swizzled) H buffers ----
#define SH_BUF   32768
#define SMEM_FUSED 98304           // 96KB -> 2 CTAs/SM

// XOR swizzle: 16B chunk cb within a row, rotated by row&7
#define SWZ(row, cb) ((((cb) ^ ((row) & 7))) * 16)

// ---------------- scratch ----------------
__device__ __half    g_h16[(size_t)NN * OUTD];            // h fp16 row-major
__device__ uint32_t  g_adjbits[(size_t)NN * NW32];        // packed adjacency (8MB)
__device__ float     g_part[(size_t)SPLITS * NN * OUTD];  // split-K partial numerators
__device__ float     g_Lp[SPLITS * NN];                   // split-K partial rowsums
__device__ __align__(16) float2 g_elx[NN];                // (exp(el), exp(.2el)) scaled
__device__ __align__(16) float2 g_erx[NN];                // (exp(er), exp(.2er)) scaled
__device__ float     g_ul[IND];
__device__ float     g_ur[IND];
__device__ float     g_cb[2];

// ---------------- helpers ----------------
__device__ __forceinline__ uint32_t smem_u32(const void* p) {
    return (uint32_t)__cvta_generic_to_shared(p);
}
__device__ __forceinline__ void cp16(void* dst, const void* src) {
    asm volatile("cp.async.cg.shared.global [%0], [%1], 16;" ::
                 "r"(smem_u32(dst)), "l"(src) : "memory");
}
__device__ __forceinline__ void cp_commit() {
    asm volatile("cp.async.commit_group;" ::: "memory");
}
__device__ __forceinline__ void cp_wait0() {
    asm volatile("cp.async.wait_group 0;" ::: "memory");
}
__device__ __forceinline__ void cp_wait1() {
    asm volatile("cp.async.wait_group 1;" ::: "memory");
}
__device__ __forceinline__ float ex2f(float x) {
    float y; asm("ex2.approx.ftz.f32 %0, %1;" : "=f"(y) : "f"(x)); return y;
}
__device__ __forceinline__ uint32_t pack2h(float a, float b) {
    return (uint32_t)__half_as_ushort(__float2half_rn(a)) |
           ((uint32_t)__half_as_ushort(__float2half_rn(b)) << 16);
}
// zero out p unless bit sh of w is set (ALU pipe; +0.0f when masked)
__device__ __forceinline__ float maskf(float p, uint32_t w, int sh) {
    uint32_t m = 0u - ((w >> sh) & 1u);
    return __uint_as_float(__float_as_uint(p) & m);
}
__device__ __forceinline__ void ldmA(uint32_t* r, const void* p) {
    uint32_t a = smem_u32(p);
    asm volatile("ldmatrix.sync.aligned.m8n8.x4.shared.b16 {%0,%1,%2,%3}, [%4];"
                 : "=r"(r[0]), "=r"(r[1]), "=r"(r[2]), "=r"(r[3]) : "r"(a));
}
__device__ __forceinline__ void ldmBT(uint32_t* r, const void* p) {
    uint32_t a = smem_u32(p);
    asm volatile("ldmatrix.sync.aligned.m8n8.x4.trans.shared.b16 {%0,%1,%2,%3}, [%4];"
                 : "=r"(r[0]), "=r"(r[1]), "=r"(r[2]), "=r"(r[3]) : "r"(a));
}
__device__ __forceinline__ void mma16816(float* c, const uint32_t* a,
                                         uint32_t b0, uint32_t b1) {
    asm volatile(
        "mma.sync.aligned.m16n8k16.row.col.f32.f16.f16.f32 "
        "{%0,%1,%2,%3},{%4,%5,%6,%7},{%8,%9},{%0,%1,%2,%3};"
        : "+f"(c[0]), "+f"(c[1]), "+f"(c[2]), "+f"(c[3])
        : "r"(a[0]), "r"(a[1]), "r"(a[2]), "r"(a[3]), "r"(b0), "r"(b1));
}

// ---------------- kernel 0: pack adjacency into bitmasks ----------------
__global__ void __launch_bounds__(256) pack_kernel(const int* __restrict__ adj) {
    const int row  = blockIdx.x;
    const int wid  = threadIdx.x >> 5;
    const int lane = threadIdx.x & 31;
    const int* arow = adj + (size_t)row * NN;
    uint32_t*  dst  = g_adjbits + (size_t)row * NW32;
    #pragma unroll 4
    for (int w = wid; w < NW32; w += 8) {
        int v = __ldcs(arow + w * 32 + lane);
        uint32_t m = __ballot_sync(0xffffffffu, v > 0);
        if (lane == 0) dst[w] = m;
    }
}

// ---------------- kernel 1: u_l = W @ a_l, u_r = W @ a_r ----------------
__global__ void __launch_bounds__(256) u_kernel(const float* __restrict__ W,
                                                const float* __restrict__ b,
                                                const float* __restrict__ a,
                                                const float* __restrict__ ab) {
    __shared__ float sa[2 * OUTD];
    const int tid = threadIdx.x;
    sa[tid]       = a[tid];
    sa[tid + 256] = a[tid + 256];
    __syncthreads();
    const int lane = tid & 31;
    const int k    = blockIdx.x * 8 + (tid >> 5);
    const float* wr = W + (size_t)k * OUTD + lane * 8;
    float4 v0 = *(const float4*)(wr);
    float4 v1 = *(const float4*)(wr + 4);
    const float* s0 = sa + lane * 8;
    const float* s1 = sa + OUTD + lane * 8;
    float ul = v0.x * s0[0] + v0.y * s0[1] + v0.z * s0[2] + v0.w * s0[3]
             + v1.x * s0[4] + v1.y * s0[5] + v1.z * s0[6] + v1.w * s0[7];
    float ur = v0.x * s1[0] + v0.y * s1[1] + v0.z * s1[2] + v0.w * s1[3]
             + v1.x * s1[4] + v1.y * s1[5] + v1.z * s1[6] + v1.w * s1[7];
    #pragma unroll
    for (int o = 16; o > 0; o >>= 1) {
        ul += __shfl_xor_sync(0xffffffffu, ul, o);
        ur += __shfl_xor_sync(0xffffffffu, ur, o);
    }
    if (lane == 0) { g_ul[k] = ul; g_ur[k] = ur; }
    if (blockIdx.x == 0 && tid == 0) {
        float bl = 0.f, br = 0.f;
        for (int n = 0; n < OUTD; ++n) {
            bl += b[n] * sa[n];
            br += b[n] * sa[OUTD + n];
        }
        g_cb[0] = bl + ab[0];
        g_cb[1] = br;
    }
}

// ---------------- kernel 2: per-node factorized exps of el/er ----------------
__global__ void __launch_bounds__(256) eler_kernel(const float* __restrict__ X) {
    __shared__ float sul[IND], sur[IND];
    const int tid = threadIdx.x;
    sul[tid]       = g_ul[tid];
    sul[tid + 256] = g_ul[tid + 256];
    sur[tid]       = g_ur[tid];
    sur[tid + 256] = g_ur[tid + 256];
    __syncthreads();
    const int lane = tid & 31;
    const int w    = tid >> 5;
    const int i    = blockIdx.x * 8 + w;
    const float* xr = X + (size_t)i * IND;
    float dl = 0.f, dr = 0.f;
    #pragma unroll
    for (int q = 0; q < 4; ++q) {
        int c = q * 128 + lane * 4;
        float4 v = *(const float4*)(xr + c);
        dl += v.x * sul[c] + v.y * sul[c + 1] + v.z * sul[c + 2] + v.w * sul[c + 3];
        dr += v.x * sur[c] + v.y * sur[c + 1] + v.z * sur[c + 2] + v.w * sur[c + 3];
    }
    #pragma unroll
    for (int o = 16; o > 0; o >>= 1) {
        dl += __shfl_xor_sync(0xffffffffu, dl, o);
        dr += __shfl_xor_sync(0xffffffffu, dr, o);
    }
    if (lane == 0) {
        float el = dl + g_cb[0];
        float er = dr + g_cb[1];
        float2 ev, fv;
        ev.x = ex2f(el * LOG2E - 3.0f);
        ev.y = ex2f(el * (0.2f * LOG2E) - 3.0f);
        fv.x = ex2f(er * LOG2E - 3.0f);
        fv.y = ex2f(er * (0.2f * LOG2E) - 3.0f);
        g_elx[i] = ev;
        g_erx[i] = fv;
    }
}

// ---------------- kernel 3: h16 = fp16(X @ W + b), row-major ----------------
__global__ void __launch_bounds__(256) gemm1_kernel(const float* __restrict__ X,
                                                    const float* __restrict__ W,
                                                    const float* __restrict__ b) {
    __shared__ __half sX[128 * 72];
    __shared__ __half sW[64 * 136];
    const int tid  = threadIdx.x;
    const int lane = tid & 31;
    const int wid  = tid >> 5;
    const int mblk = blockIdx.x * 128;
    const int nblk = blockIdx.y * 128;
    const int wm   = (wid >> 1) * 32;
    const int wn   = (wid & 1) * 64;

    float acc[2][8][4];
    #pragma unroll
    for (int i = 0; i < 2; ++i)
        #pragma unroll
        for (int j = 0; j < 8; ++j)
            #pragma unroll
            for (int k = 0; k < 4; ++k) acc[i][j][k] = 0.f;

    for (int k0 = 0; k0 < IND; k0 += 64) {
        __syncthreads();
        #pragma unroll
        for (int pass = 0; pass < 8; ++pass) {
            int row = pass * 16 + (tid >> 4);
            int col = (tid & 15) * 4;
            float4 v = *(const float4*)(X + (size_t)(mblk + row) * IND + k0 + col);
            *(__half2*)&sX[row * 72 + col]     = __floats2half2_rn(v.x, v.y);
            *(__half2*)&sX[row * 72 + col + 2] = __floats2half2_rn(v.z, v.w);
        }
        #pragma unroll
        for (int pass = 0; pass < 8; ++pass) {
            int row = pass * 8 + (tid >> 5);
            int col = (tid & 31) * 4;
            float4 v = *(const float4*)(W + (size_t)(k0 + row) * OUTD + nblk + col);
            *(__half2*)&sW[row * 136 + col]     = __floats2half2_rn(v.x, v.y);
            *(__half2*)&sW[row * 136 + col + 2] = __floats2half2_rn(v.z, v.w);
        }
        __syncthreads();
        #pragma unroll
        for (int kk = 0; kk < 4; ++kk) {
            int kb = kk * 16;
            uint32_t A[2][4];
            #pragma unroll
            for (int mf = 0; mf < 2; ++mf)
                ldmA(A[mf], &sX[(wm + mf * 16 + (lane & 15)) * 72 + kb + (lane >> 4) * 8]);
            #pragma unroll
            for (int nf = 0; nf < 4; ++nf) {
                uint32_t B[4];
                ldmBT(B, &sW[(kb + (lane & 15)) * 136 + wn + nf * 16 + (lane >> 4) * 8]);
                #pragma unroll
                for (int mf = 0; mf < 2; ++mf) {
                    mma16816(acc[mf][2 * nf],     A[mf], B[0], B[1]);
                    mma16816(acc[mf][2 * nf + 1], A[mf], B[2], B[3]);
                }
            }
        }
    }
    #pragma unroll
    for (int mf = 0; mf < 2; ++mf) {
        int grow = mblk + wm + mf * 16 + (lane >> 2);
        #pragma unroll
        for (int nf = 0; nf < 8; ++nf) {
            int gcol = nblk + wn + nf * 8 + (lane & 3) * 2;
            float b0 = b[gcol], b1 = b[gcol + 1];
            *(__half2*)&g_h16[(size_t)grow * OUTD + gcol] =
                __floats2half2_rn(acc[mf][nf][0] + b0, acc[mf][nf][1] + b1);
            *(__half2*)&g_h16[(size_t)(grow + 8) * OUTD + gcol] =
                __floats2half2_rn(acc[mf][nf][2] + b0, acc[mf][nf][3] + b1);
        }
    }
}

// ---------------- kernel 4: fused attention — P computed directly in A-frags ----
__global__ void __launch_bounds__(256, 2) gat_fused_kernel() {
    extern __shared__ __align__(1024) char smem[];

    const int tid  = threadIdx.x;
    const int lane = tid & 31;
    const int wid  = tid >> 5;
    const int lq   = lane >> 2;       // groupID (A-frag row within 8)
    const int tig  = lane & 3;        // thread-in-group (A-frag col pair)
    const int s    = blockIdx.x & 1;
    const int rb   = blockIdx.x >> 1;
    const int i0   = rb * BM;
    const int J0   = s * JRANGE;

    const int wm = (wid >> 2) * 32;   // row group (0 / 32)
    const int wn = (wid & 3) * 64;    // col group

    // per-thread A-frag rows: R[j] = wm + 16*(j>>1) + 8*(j&1) + lq, j=2*mf+h
    float2 ev[4];
    const uint2* bptr[4];
    #pragma unroll
    for (int j = 0; j < 4; ++j) {
        int R = i0 + wm + 16 * (j >> 1) + 8 * (j & 1) + lq;
        ev[j] = g_elx[R];
        bptr[j] = (const uint2*)(g_adjbits + (size_t)R * NW32 + (J0 >> 5));
    }

    // prologue: stage H tiles 0 and 1
    #pragma unroll
    for (int tt = 0; tt < 2; ++tt) {
        #pragma unroll
        for (int p = 0; p < 8; ++p) {
            int idx = p * 256 + tid;
            int row = idx >> 5, cb = idx & 31;
            cp16(smem + tt * SH_BUF + row * 512 + SWZ(row, cb),
                 g_h16 + (size_t)(J0 + tt * BK + row) * OUTD + cb * 8);
        }
        cp_commit();
    }

    uint2 bits_c[4], bits_n[4];
    #pragma unroll
    for (int j = 0; j < 4; ++j) bits_c[j] = bptr[j][0];

    float acc[2][8][4];
    #pragma unroll
    for (int i = 0; i < 2; ++i)
        #pragma unroll
        for (int j = 0; j < 8; ++j)
            #pragma unroll
            for (int k = 0; k < 4; ++k) acc[i][j][k] = 0.f;
    float psum[4] = {0.f, 0.f, 0.f, 0.f};

    const int cb0 = tig << 1;

    for (int t = 0; t < NTILES; ++t) {
        const int jb = J0 + t * BK;

        // first erx pair for this tile — issue before the wait to hide latency
        float4 u0 = *(const float4*)(g_erx + jb + cb0);
        float4 u1 = *(const float4*)(g_erx + jb + cb0 + 8);

        if (t < NTILES - 1) cp_wait1();
        else                cp_wait0();
        __syncthreads();   // H[t] visible to all; MMA[t-1] done by all

        // issue H cp for tile t+2 (buffer (t+2)%3 == (t-1)%3, free after sync)
        if (t + 2 < NTILES) {
            const int nb = (t + 2) % 3;
            const int jn = J0 + (t + 2) * BK;
            #pragma unroll
            for (int p = 0; p < 8; ++p) {
                int idx = p * 256 + tid;
                int row = idx >> 5, cb = idx & 31;
                cp16(smem + nb * SH_BUF + row * 512 + SWZ(row, cb),
                     g_h16 + (size_t)(jn + row) * OUTD + cb * 8);
            }
            cp_commit();
        }

        // prefetch adjacency bits for tile t+1
        if (t + 1 < NTILES) {
            #pragma unroll
            for (int j = 0; j < 4; ++j) bits_n[j] = bptr[j][t + 1];
        }

        const char* sHb = smem + (t % 3) * SH_BUF;

        #pragma unroll
        for (int kk = 0; kk < 4; ++kk) {
            // pipeline next kk's erx loads
            float4 n0, n1;
            if (kk < 3) {
                const int cbn = cb0 + ((kk + 1) << 4);
                n0 = *(const float4*)(g_erx + jb + cbn);
                n1 = *(const float4*)(g_erx + jb + cbn + 8);
            }

            // build A fragments: p = mask * max(e1l*e1r, e2l*e2r)
            const int sh = (cb0 + (kk << 4)) & 31;
            uint32_t A[2][4];
            #pragma unroll
            for (int j = 0; j < 4; ++j) {
                const int mf = j >> 1, h = j & 1;
                const uint32_t w = (kk < 2) ? bits_c[j].x : bits_c[j].y;
                const float2 e = ev[j];
                float p0 = fmaxf(e.x * u0.x, e.y * u0.y);
                float p1 = fmaxf(e.x * u0.z, e.y * u0.w);
                float p8 = fmaxf(e.x * u1.x, e.y * u1.y);
                float p9 = fmaxf(e.x * u1.z, e.y * u1.w);
                p0 = maskf(p0, w, sh);
                p1 = maskf(p1, w, sh + 1);
                p8 = maskf(p8, w, sh + 8);
                p9 = maskf(p9, w, sh + 9);
                psum[j] += (p0 + p1) + (p8 + p9);
                A[mf][h]     = pack2h(p0, p1);
                A[mf][2 + h] = pack2h(p8, p9);
            }

            // B loads + MMA
            const int krow = (kk << 4) + (lane & 15);
            const char* hb = sHb + krow * 512;
            #pragma unroll
            for (int nf = 0; nf < 4; ++nf) {
                uint32_t B[4];
                ldmBT(B, hb + SWZ(krow, (wn >> 3) + nf * 2 + (lane >> 4)));
                mma16816(acc[0][2 * nf],     A[0], B[0], B[1]);
                mma16816(acc[0][2 * nf + 1], A[0], B[2], B[3]);
                mma16816(acc[1][2 * nf],     A[1], B[0], B[1]);
                mma16816(acc[1][2 * nf + 1], A[1], B[2], B[3]);
            }
            u0 = n0; u1 = n1;
        }

        #pragma unroll
        for (int j = 0; j < 4; ++j) bits_c[j] = bits_n[j];
    }

    // rowsum: quad-reduce (lanes tig=0..3 hold disjoint col quarters of each row)
    #pragma unroll
    for (int j = 0; j < 4; ++j) {
        psum[j] += __shfl_xor_sync(0xffffffffu, psum[j], 1);
        psum[j] += __shfl_xor_sync(0xffffffffu, psum[j], 2);
    }
    if ((wid & 3) == 0 && tig == 0) {
        #pragma unroll
        for (int j = 0; j < 4; ++j)
            g_Lp[s * NN + i0 + wm + 16 * (j >> 1) + 8 * (j & 1) + lq] = psum[j];
    }

    // write partial numerators
    #pragma unroll
    for (int mf = 0; mf < 2; ++mf) {
        int row0 = wm + mf * 16 + lq;
        float* d0 = g_part + ((size_t)s * NN + i0 + row0) * OUTD;
        float* d1 = g_part + ((size_t)s * NN + i0 + row0 + 8) * OUTD;
        #pragma unroll
        for (int nf = 0; nf < 8; ++nf) {
            int col = wn + nf * 8 + tig * 2;
            *(float2*)(d0 + col) = make_float2(acc[mf][nf][0], acc[mf][nf][1]);
            *(float2*)(d1 + col) = make_float2(acc[mf][nf][2], acc[mf][nf][3]);
        }
    }
}

// ---------------- kernel 5: combine split-K partials ----------------
__global__ void __launch_bounds__(256) combine_kernel(float* __restrict__ out) {
    const int gid = blockIdx.x * 256 + threadIdx.x;
    const int row = gid >> 6;
    const int c   = (gid & 63) * 4;
    const float4 x0 = *(const float4*)(g_part + (size_t)row * OUTD + c);
    const float4 x1 = *(const float4*)(g_part + (size_t)NN * OUTD + (size_t)row * OUTD + c);
    const float inv = 1.0f / (g_Lp[row] + g_Lp[NN + row]);
    float4 o;
    o.x = (x0.x + x1.x) * inv;
    o.y = (x0.y + x1.y) * inv;
    o.z = (x0.z + x1.z) * inv;
    o.w = (x0.w + x1.w) * inv;
    *(float4*)(out + (size_t)row * OUTD + c) = o;
}

// ---------------- launch ----------------
extern "C" void kernel_launch(void* const* d_in, const int* in_sizes, int n_in,
                              void* d_out, int out_size) {
    const int*   adj = (const int*)d_in[0];
    const float* X   = (const float*)d_in[1];
    const float* W   = (const float*)d_in[2];
    const float* b   = (const float*)d_in[3];
    const float* a   = (const float*)d_in[4];
    const float* ab  = (const float*)d_in[5];
    float* out = (float*)d_out;

    cudaFuncSetAttribute(gat_fused_kernel,
                         cudaFuncAttributeMaxDynamicSharedMemorySize, SMEM_FUSED);

    pack_kernel<<<NN, 256>>>(adj);
    u_kernel<<<64, 256>>>(W, b, a, ab);
    eler_kernel<<<NN / 8, 256>>>(X);
    gemm1_kernel<<<dim3(NN / 128, OUTD / 128), 256>>>(X, W, b);
    gat_fused_kernel<<<(NN / BM) * SPLITS, 256, SMEM_FUSED>>>();
    combine_kernel<<<(NN * OUTD / 4) / 256, 256>>>(out);
}

// round 7
// speedup vs baseline: 1.2912x; 1.2912x over previous
#include <cuda_runtime.h>
#include <cuda_fp16.h>
#include <cstdint>

#define NN    8192
#define IND   512
#define OUTD  256
#define BM    64
#define BK    64
#define SPLITS 2
#define JRANGE (NN / SPLITS)      // 4096
#define NTILES (JRANGE / BK)      // 64
#define NW32   (NN / 32)          // 256 mask words per row
#define LOG2E 1.4426950408889634f

// ---- dynamic smem: 3 x (64 rows x 512B swizzled) H + 3 x 512B er ----
#define SH_BUF   32768
#define SER_OFF  98304
#define SMEM_FUSED 99840           // <= 112KB -> 2 CTAs/SM

// XOR swizzle: 16B chunk cb within a row, rotated by row&7
#define SWZ(row, cb) ((((cb) ^ ((row) & 7))) * 16)

// ---------------- scratch ----------------
__device__ __half    g_h16[(size_t)NN * OUTD];            // h fp16 row-major
__device__ uint32_t  g_adjbits[(size_t)NN * NW32];        // packed adjacency (8MB)
__device__ float     g_part[(size_t)SPLITS * NN * OUTD];  // split-K partial numerators
__device__ float     g_Lp[SPLITS * NN];                   // split-K partial rowsums
__device__ __align__(16) float2 g_elx[NN];                // (exp(el), exp(.2el)) scaled
__device__ __align__(16) float2 g_erx[NN];                // (exp(er), exp(.2er)) scaled
__device__ float     g_ul[IND];
__device__ float     g_ur[IND];
__device__ float     g_cb[2];

// ---------------- helpers ----------------
__device__ __forceinline__ uint32_t smem_u32(const void* p) {
    return (uint32_t)__cvta_generic_to_shared(p);
}
__device__ __forceinline__ void cp16(void* dst, const void* src) {
    asm volatile("cp.async.cg.shared.global [%0], [%1], 16;" ::
                 "r"(smem_u32(dst)), "l"(src) : "memory");
}
__device__ __forceinline__ void cp_commit() {
    asm volatile("cp.async.commit_group;" ::: "memory");
}
__device__ __forceinline__ void cp_wait0() {
    asm volatile("cp.async.wait_group 0;" ::: "memory");
}
__device__ __forceinline__ void cp_wait1() {
    asm volatile("cp.async.wait_group 1;" ::: "memory");
}
__device__ __forceinline__ float ex2f(float x) {
    float y; asm("ex2.approx.ftz.f32 %0, %1;" : "=f"(y) : "f"(x)); return y;
}
// single-SASS pack of two floats to half2 (F2FP.PACK_AB)
__device__ __forceinline__ uint32_t pack2h(float a, float b) {
    __half2 h = __floats2half2_rn(a, b);
    return *reinterpret_cast<uint32_t*>(&h);
}
// zero out p unless bit sh of w is set (ALU pipe; +0.0f when masked)
__device__ __forceinline__ float maskf(float p, uint32_t w, int sh) {
    uint32_t m = 0u - ((w >> sh) & 1u);
    return __uint_as_float(__float_as_uint(p) & m);
}
__device__ __forceinline__ void ldmA(uint32_t* r, const void* p) {
    uint32_t a = smem_u32(p);
    asm volatile("ldmatrix.sync.aligned.m8n8.x4.shared.b16 {%0,%1,%2,%3}, [%4];"
                 : "=r"(r[0]), "=r"(r[1]), "=r"(r[2]), "=r"(r[3]) : "r"(a));
}
__device__ __forceinline__ void ldmBT(uint32_t* r, const void* p) {
    uint32_t a = smem_u32(p);
    asm volatile("ldmatrix.sync.aligned.m8n8.x4.trans.shared.b16 {%0,%1,%2,%3}, [%4];"
                 : "=r"(r[0]), "=r"(r[1]), "=r"(r[2]), "=r"(r[3]) : "r"(a));
}
__device__ __forceinline__ void mma16816(float* c, const uint32_t* a,
                                         uint32_t b0, uint32_t b1) {
    asm volatile(
        "mma.sync.aligned.m16n8k16.row.col.f32.f16.f16.f32 "
        "{%0,%1,%2,%3},{%4,%5,%6,%7},{%8,%9},{%0,%1,%2,%3};"
        : "+f"(c[0]), "+f"(c[1]), "+f"(c[2]), "+f"(c[3])
        : "r"(a[0]), "r"(a[1]), "r"(a[2]), "r"(a[3]), "r"(b0), "r"(b1));
}

// ---------------- kernel 0: pack adjacency into bitmasks (int4 + shfl-or) ------
__global__ void __launch_bounds__(256) pack_kernel(const int* __restrict__ adj) {
    const int row  = blockIdx.x;
    const int tid  = threadIdx.x;
    const int lane = tid & 31;
    const int4* arow = (const int4*)(adj + (size_t)row * NN);
    uint32_t*   dst  = g_adjbits + (size_t)row * NW32;
    #pragma unroll
    for (int it = 0; it < 8; ++it) {
        int idx = it * 256 + tid;                 // int4 index: cols 4*idx..4*idx+3
        int4 v = __ldcs(arow + idx);
        uint32_t nib = (uint32_t)(v.x > 0) | ((uint32_t)(v.y > 0) << 1)
                     | ((uint32_t)(v.z > 0) << 2) | ((uint32_t)(v.w > 0) << 3);
        uint32_t m = nib << ((lane & 7) * 4);
        m |= __shfl_xor_sync(0xffffffffu, m, 1);
        m |= __shfl_xor_sync(0xffffffffu, m, 2);
        m |= __shfl_xor_sync(0xffffffffu, m, 4);
        if ((lane & 7) == 0) dst[idx >> 3] = m;   // 8 int4 = 32 cols per word
    }
}

// ---------------- kernel 1: u_l = W @ a_l, u_r = W @ a_r ----------------
__global__ void __launch_bounds__(256) u_kernel(const float* __restrict__ W,
                                                const float* __restrict__ b,
                                                const float* __restrict__ a,
                                                const float* __restrict__ ab) {
    __shared__ float sa[2 * OUTD];
    const int tid = threadIdx.x;
    sa[tid]       = a[tid];
    sa[tid + 256] = a[tid + 256];
    __syncthreads();
    const int lane = tid & 31;
    const int k    = blockIdx.x * 8 + (tid >> 5);
    const float* wr = W + (size_t)k * OUTD + lane * 8;
    float4 v0 = *(const float4*)(wr);
    float4 v1 = *(const float4*)(wr + 4);
    const float* s0 = sa + lane * 8;
    const float* s1 = sa + OUTD + lane * 8;
    float ul = v0.x * s0[0] + v0.y * s0[1] + v0.z * s0[2] + v0.w * s0[3]
             + v1.x * s0[4] + v1.y * s0[5] + v1.z * s0[6] + v1.w * s0[7];
    float ur = v0.x * s1[0] + v0.y * s1[1] + v0.z * s1[2] + v0.w * s1[3]
             + v1.x * s1[4] + v1.y * s1[5] + v1.z * s1[6] + v1.w * s1[7];
    #pragma unroll
    for (int o = 16; o > 0; o >>= 1) {
        ul += __shfl_xor_sync(0xffffffffu, ul, o);
        ur += __shfl_xor_sync(0xffffffffu, ur, o);
    }
    if (lane == 0) { g_ul[k] = ul; g_ur[k] = ur; }
    if (blockIdx.x == 0 && tid == 0) {
        float bl = 0.f, br = 0.f;
        for (int n = 0; n < OUTD; ++n) {
            bl += b[n] * sa[n];
            br += b[n] * sa[OUTD + n];
        }
        g_cb[0] = bl + ab[0];
        g_cb[1] = br;
    }
}

// ---------------- kernel 2: per-node factorized exps of el/er ----------------
__global__ void __launch_bounds__(256) eler_kernel(const float* __restrict__ X) {
    __shared__ float sul[IND], sur[IND];
    const int tid = threadIdx.x;
    sul[tid]       = g_ul[tid];
    sul[tid + 256] = g_ul[tid + 256];
    sur[tid]       = g_ur[tid];
    sur[tid + 256] = g_ur[tid + 256];
    __syncthreads();
    const int lane = tid & 31;
    const int w    = tid >> 5;
    const int i    = blockIdx.x * 8 + w;
    const float* xr = X + (size_t)i * IND;
    float dl = 0.f, dr = 0.f;
    #pragma unroll
    for (int q = 0; q < 4; ++q) {
        int c = q * 128 + lane * 4;
        float4 v = *(const float4*)(xr + c);
        dl += v.x * sul[c] + v.y * sul[c + 1] + v.z * sul[c + 2] + v.w * sul[c + 3];
        dr += v.x * sur[c] + v.y * sur[c + 1] + v.z * sur[c + 2] + v.w * sur[c + 3];
    }
    #pragma unroll
    for (int o = 16; o > 0; o >>= 1) {
        dl += __shfl_xor_sync(0xffffffffu, dl, o);
        dr += __shfl_xor_sync(0xffffffffu, dr, o);
    }
    if (lane == 0) {
        float el = dl + g_cb[0];
        float er = dr + g_cb[1];
        float2 ev, fv;
        ev.x = ex2f(el * LOG2E - 3.0f);
        ev.y = ex2f(el * (0.2f * LOG2E) - 3.0f);
        fv.x = ex2f(er * LOG2E - 3.0f);
        fv.y = ex2f(er * (0.2f * LOG2E) - 3.0f);
        g_elx[i] = ev;
        g_erx[i] = fv;
    }
}

// ---------------- kernel 3: h16 = fp16(X @ W + b), row-major ----------------
__global__ void __launch_bounds__(256) gemm1_kernel(const float* __restrict__ X,
                                                    const float* __restrict__ W,
                                                    const float* __restrict__ b) {
    __shared__ __half sX[128 * 72];
    __shared__ __half sW[64 * 136];
    const int tid  = threadIdx.x;
    const int lane = tid & 31;
    const int wid  = tid >> 5;
    const int mblk = blockIdx.x * 128;
    const int nblk = blockIdx.y * 128;
    const int wm   = (wid >> 1) * 32;
    const int wn   = (wid & 1) * 64;

    float acc[2][8][4];
    #pragma unroll
    for (int i = 0; i < 2; ++i)
        #pragma unroll
        for (int j = 0; j < 8; ++j)
            #pragma unroll
            for (int k = 0; k < 4; ++k) acc[i][j][k] = 0.f;

    for (int k0 = 0; k0 < IND; k0 += 64) {
        __syncthreads();
        #pragma unroll
        for (int pass = 0; pass < 8; ++pass) {
            int row = pass * 16 + (tid >> 4);
            int col = (tid & 15) * 4;
            float4 v = *(const float4*)(X + (size_t)(mblk + row) * IND + k0 + col);
            *(__half2*)&sX[row * 72 + col]     = __floats2half2_rn(v.x, v.y);
            *(__half2*)&sX[row * 72 + col + 2] = __floats2half2_rn(v.z, v.w);
        }
        #pragma unroll
        for (int pass = 0; pass < 8; ++pass) {
            int row = pass * 8 + (tid >> 5);
            int col = (tid & 31) * 4;
            float4 v = *(const float4*)(W + (size_t)(k0 + row) * OUTD + nblk + col);
            *(__half2*)&sW[row * 136 + col]     = __floats2half2_rn(v.x, v.y);
            *(__half2*)&sW[row * 136 + col + 2] = __floats2half2_rn(v.z, v.w);
        }
        __syncthreads();
        #pragma unroll
        for (int kk = 0; kk < 4; ++kk) {
            int kb = kk * 16;
            uint32_t A[2][4];
            #pragma unroll
            for (int mf = 0; mf < 2; ++mf)
                ldmA(A[mf], &sX[(wm + mf * 16 + (lane & 15)) * 72 + kb + (lane >> 4) * 8]);
            #pragma unroll
            for (int nf = 0; nf < 4; ++nf) {
                uint32_t B[4];
                ldmBT(B, &sW[(kb + (lane & 15)) * 136 + wn + nf * 16 + (lane >> 4) * 8]);
                #pragma unroll
                for (int mf = 0; mf < 2; ++mf) {
                    mma16816(acc[mf][2 * nf],     A[mf], B[0], B[1]);
                    mma16816(acc[mf][2 * nf + 1], A[mf], B[2], B[3]);
                }
            }
        }
    }
    #pragma unroll
    for (int mf = 0; mf < 2; ++mf) {
        int grow = mblk + wm + mf * 16 + (lane >> 2);
        #pragma unroll
        for (int nf = 0; nf < 8; ++nf) {
            int gcol = nblk + wn + nf * 8 + (lane & 3) * 2;
            float b0 = b[gcol], b1 = b[gcol + 1];
            *(__half2*)&g_h16[(size_t)grow * OUTD + gcol] =
                __floats2half2_rn(acc[mf][nf][0] + b0, acc[mf][nf][1] + b1);
            *(__half2*)&g_h16[(size_t)(grow + 8) * OUTD + gcol] =
                __floats2half2_rn(acc[mf][nf][2] + b0, acc[mf][nf][3] + b1);
        }
    }
}

// ---------------- kernel 4: fused attention — register A-frags, smem er --------
__global__ void __launch_bounds__(256, 2) gat_fused_kernel() {
    extern __shared__ __align__(1024) char smem[];

    const int tid  = threadIdx.x;
    const int lane = tid & 31;
    const int wid  = tid >> 5;
    const int lq   = lane >> 2;       // A-frag row within 8
    const int tig  = lane & 3;        // A-frag col pair
    const int s    = blockIdx.x & 1;
    const int rb   = blockIdx.x >> 1;
    const int i0   = rb * BM;
    const int J0   = s * JRANGE;

    const int wm = (wid >> 2) * 32;   // row group (0 / 32)
    const int wn = (wid & 3) * 64;    // col group
    const bool do_psum = (wid & 3) == 0;

    // per-thread A-frag rows: R[j] = wm + 16*(j>>1) + 8*(j&1) + lq
    float2 ev[4];
    const uint2* bptr[4];
    #pragma unroll
    for (int j = 0; j < 4; ++j) {
        int R = i0 + wm + 16 * (j >> 1) + 8 * (j & 1) + lq;
        ev[j] = g_elx[R];
        bptr[j] = (const uint2*)(g_adjbits + (size_t)R * NW32 + (J0 >> 5));
    }

    // prologue: stage H + er for tiles 0 and 1
    #pragma unroll
    for (int tt = 0; tt < 2; ++tt) {
        #pragma unroll
        for (int p = 0; p < 8; ++p) {
            int idx = p * 256 + tid;
            int row = idx >> 5, cb = idx & 31;
            cp16(smem + tt * SH_BUF + row * 512 + SWZ(row, cb),
                 g_h16 + (size_t)(J0 + tt * BK + row) * OUTD + cb * 8);
        }
        if (tid < 32) cp16(smem + SER_OFF + tt * 512 + tid * 16,
                           g_erx + J0 + tt * BK + tid * 2);
        cp_commit();
    }

    uint2 bits_c[4], bits_n[4];
    #pragma unroll
    for (int j = 0; j < 4; ++j) bits_c[j] = bptr[j][0];

    float acc[2][8][4];
    #pragma unroll
    for (int i = 0; i < 2; ++i)
        #pragma unroll
        for (int j = 0; j < 8; ++j)
            #pragma unroll
            for (int k = 0; k < 4; ++k) acc[i][j][k] = 0.f;
    float psum[4] = {0.f, 0.f, 0.f, 0.f};

    const int cb0 = tig << 1;

    for (int t = 0; t < NTILES; ++t) {
        if (t < NTILES - 1) cp_wait1();
        else                cp_wait0();
        __syncthreads();   // H[t]/er[t] visible to all; MMA[t-1] done by all

        // issue H + er cp for tile t+2 (buffer (t+2)%3, free after sync)
        if (t + 2 < NTILES) {
            const int nb = (t + 2) % 3;
            const int jn = J0 + (t + 2) * BK;
            #pragma unroll
            for (int p = 0; p < 8; ++p) {
                int idx = p * 256 + tid;
                int row = idx >> 5, cb = idx & 31;
                cp16(smem + nb * SH_BUF + row * 512 + SWZ(row, cb),
                     g_h16 + (size_t)(jn + row) * OUTD + cb * 8);
            }
            if (tid < 32) cp16(smem + SER_OFF + nb * 512 + tid * 16,
                               g_erx + jn + tid * 2);
            cp_commit();
        }

        // prefetch adjacency bits for tile t+1
        if (t + 1 < NTILES) {
            #pragma unroll
            for (int j = 0; j < 4; ++j) bits_n[j] = bptr[j][t + 1];
        }

        const char*   sHb = smem + (t % 3) * SH_BUF;
        const float4* se  = (const float4*)(smem + SER_OFF + (t % 3) * 512);

        // er factors for kk=0 (LDS broadcast)
        float4 u0 = se[tig];       // cols cb0, cb0+1
        float4 u1 = se[tig + 4];   // cols cb0+8, cb0+9

        #pragma unroll
        for (int kk = 0; kk < 4; ++kk) {
            // prefetch next kk's er factors
            float4 n0, n1;
            if (kk < 3) {
                n0 = se[tig + 8 * (kk + 1)];
                n1 = se[tig + 4 + 8 * (kk + 1)];
            }

            // build A fragments: p = mask & max(e1l*e1r, e2l*e2r)
            const int sh = (cb0 + (kk << 4)) & 31;
            uint32_t A[2][4];
            #pragma unroll
            for (int j = 0; j < 4; ++j) {
                const int mf = j >> 1, h = j & 1;
                const uint32_t w = (kk < 2) ? bits_c[j].x : bits_c[j].y;
                const float2 e = ev[j];
                float p0 = fmaxf(e.x * u0.x, e.y * u0.y);
                float p1 = fmaxf(e.x * u0.z, e.y * u0.w);
                float p8 = fmaxf(e.x * u1.x, e.y * u1.y);
                float p9 = fmaxf(e.x * u1.z, e.y * u1.w);
                p0 = maskf(p0, w, sh);
                p1 = maskf(p1, w, sh + 1);
                p8 = maskf(p8, w, sh + 8);
                p9 = maskf(p9, w, sh + 9);
                if (do_psum) psum[j] += (p0 + p1) + (p8 + p9);
                A[mf][h]     = pack2h(p0, p1);
                A[mf][2 + h] = pack2h(p8, p9);
            }

            // B loads + MMA
            const int krow = (kk << 4) + (lane & 15);
            const char* hb = sHb + krow * 512;
            #pragma unroll
            for (int nf = 0; nf < 4; ++nf) {
                uint32_t B[4];
                ldmBT(B, hb + SWZ(krow, (wn >> 3) + nf * 2 + (lane >> 4)));
                mma16816(acc[0][2 * nf],     A[0], B[0], B[1]);
                mma16816(acc[0][2 * nf + 1], A[0], B[2], B[3]);
                mma16816(acc[1][2 * nf],     A[1], B[0], B[1]);
                mma16816(acc[1][2 * nf + 1], A[1], B[2], B[3]);
            }
            u0 = n0; u1 = n1;
        }

        #pragma unroll
        for (int j = 0; j < 4; ++j) bits_c[j] = bits_n[j];
    }

    // rowsum: quad-reduce over tig lanes (colG-0 warps hold valid psums)
    #pragma unroll
    for (int j = 0; j < 4; ++j) {
        psum[j] += __shfl_xor_sync(0xffffffffu, psum[j], 1);
        psum[j] += __shfl_xor_sync(0xffffffffu, psum[j], 2);
    }
    if (do_psum && tig == 0) {
        #pragma unroll
        for (int j = 0; j < 4; ++j)
            g_Lp[s * NN + i0 + wm + 16 * (j >> 1) + 8 * (j & 1) + lq] = psum[j];
    }

    // write partial numerators
    #pragma unroll
    for (int mf = 0; mf < 2; ++mf) {
        int row0 = wm + mf * 16 + lq;
        float* d0 = g_part + ((size_t)s * NN + i0 + row0) * OUTD;
        float* d1 = g_part + ((size_t)s * NN + i0 + row0 + 8) * OUTD;
        #pragma unroll
        for (int nf = 0; nf < 8; ++nf) {
            int col = wn + nf * 8 + tig * 2;
            *(float2*)(d0 + col) = make_float2(acc[mf][nf][0], acc[mf][nf][1]);
            *(float2*)(d1 + col) = make_float2(acc[mf][nf][2], acc[mf][nf][3]);
        }
    }
}

// ---------------- kernel 5: combine split-K partials ----------------
__global__ void __launch_bounds__(256) combine_kernel(float* __restrict__ out) {
    const int gid = blockIdx.x * 256 + threadIdx.x;
    const int row = gid >> 6;
    const int c   = (gid & 63) * 4;
    const float4 x0 = *(const float4*)(g_part + (size_t)row * OUTD + c);
    const float4 x1 = *(const float4*)(g_part + (size_t)NN * OUTD + (size_t)row * OUTD + c);
    const float inv = 1.0f / (g_Lp[row] + g_Lp[NN + row]);
    float4 o;
    o.x = (x0.x + x1.x) * inv;
    o.y = (x0.y + x1.y) * inv;
    o.z = (x0.z + x1.z) * inv;
    o.w = (x0.w + x1.w) * inv;
    *(float4*)(out + (size_t)row * OUTD + c) = o;
}

// ---------------- launch ----------------
extern "C" void kernel_launch(void* const* d_in, const int* in_sizes, int n_in,
                              void* d_out, int out_size) {
    const int*   adj = (const int*)d_in[0];
    const float* X   = (const float*)d_in[1];
    const float* W   = (const float*)d_in[2];
    const float* b   = (const float*)d_in[3];
    const float* a   = (const float*)d_in[4];
    const float* ab  = (const float*)d_in[5];
    float* out = (float*)d_out;

    cudaFuncSetAttribute(gat_fused_kernel,
                         cudaFuncAttributeMaxDynamicSharedMemorySize, SMEM_FUSED);

    u_kernel<<<64, 256>>>(W, b, a, ab);
    eler_kernel<<<NN / 8, 256>>>(X);
    pack_kernel<<<NN, 256>>>(adj);
    gemm1_kernel<<<dim3(NN / 128, OUTD / 128), 256>>>(X, W, b);
    gat_fused_kernel<<<(NN / BM) * SPLITS, 256, SMEM_FUSED>>>();
    combine_kernel<<<(NN * OUTD / 4) / 256, 256>>>(out);
}

// round 8
// speedup vs baseline: 1.5338x; 1.1878x over previous
#include <cuda_runtime.h>
#include <cuda_fp16.h>
#include <cstdint>

#define NN    8192
#define IND   512
#define OUTD  256
#define BM    64
#define BK    64
#define SPLITS 2
#define JRANGE (NN / SPLITS)      // 4096
#define NTILES (JRANGE / BK)      // 64
#define LOG2E 1.4426950408889634f

// ---- dynamic smem (bytes) ----
// sP : 2 x (64 rows x 128B swizzled) = 16384 @ 0
// sH : 2 x (64 rows x 512B swizzled) = 65536 @ 16384
// sEr: 3 x 512B                      =  1536 @ 81920
#define SP_OFF   0
#define SP_BUF   8192
#define SH_OFF   16384
#define SH_BUF   32768
#define SER_OFF  81920
#define SMEM_FUSED 83456           // 2 CTAs/SM, ~60KB L1 left

// XOR swizzle: 16B chunk cb within a row, rotated by row&7
#define SWZ(row, cb) ((((cb) ^ ((row) & 7))) * 16)

// ---------------- scratch ----------------
__device__ __half    g_h16[(size_t)NN * OUTD];            // h fp16 row-major
__device__ float     g_part[(size_t)SPLITS * NN * OUTD];  // split-K partial numerators
__device__ float     g_Lp[SPLITS * NN];                   // split-K partial rowsums
__device__ __align__(16) float2 g_elx[NN];                // (exp(el), exp(.2el)) scaled
__device__ __align__(16) float2 g_erx[NN];                // (exp(er), exp(.2er)) scaled
__device__ float     g_ul[IND];
__device__ float     g_ur[IND];
__device__ float     g_cb[2];

// ---------------- helpers ----------------
__device__ __forceinline__ uint32_t smem_u32(const void* p) {
    return (uint32_t)__cvta_generic_to_shared(p);
}
__device__ __forceinline__ void cp16(void* dst, const void* src) {
    asm volatile("cp.async.cg.shared.global [%0], [%1], 16;" ::
                 "r"(smem_u32(dst)), "l"(src) : "memory");
}
__device__ __forceinline__ void cp_commit() {
    asm volatile("cp.async.commit_group;" ::: "memory");
}
__device__ __forceinline__ void cp_wait0() {
    asm volatile("cp.async.wait_group 0;" ::: "memory");
}
__device__ __forceinline__ float ex2f(float x) {
    float y; asm("ex2.approx.ftz.f32 %0, %1;" : "=f"(y) : "f"(x)); return y;
}
// single-SASS pack of two floats to half2 (F2FP.PACK_AB)
__device__ __forceinline__ uint32_t pack2h(float a, float b) {
    __half2 h = __floats2half2_rn(a, b);
    return *reinterpret_cast<uint32_t*>(&h);
}
__device__ __forceinline__ void ldmA(uint32_t* r, const void* p) {
    uint32_t a = smem_u32(p);
    asm volatile("ldmatrix.sync.aligned.m8n8.x4.shared.b16 {%0,%1,%2,%3}, [%4];"
                 : "=r"(r[0]), "=r"(r[1]), "=r"(r[2]), "=r"(r[3]) : "r"(a));
}
__device__ __forceinline__ void ldmBT(uint32_t* r, const void* p) {
    uint32_t a = smem_u32(p);
    asm volatile("ldmatrix.sync.aligned.m8n8.x4.trans.shared.b16 {%0,%1,%2,%3}, [%4];"
                 : "=r"(r[0]), "=r"(r[1]), "=r"(r[2]), "=r"(r[3]) : "r"(a));
}
__device__ __forceinline__ void mma16816(float* c, const uint32_t* a,
                                         uint32_t b0, uint32_t b1) {
    asm volatile(
        "mma.sync.aligned.m16n8k16.row.col.f32.f16.f16.f32 "
        "{%0,%1,%2,%3},{%4,%5,%6,%7},{%8,%9},{%0,%1,%2,%3};"
        : "+f"(c[0]), "+f"(c[1]), "+f"(c[2]), "+f"(c[3])
        : "r"(a[0]), "r"(a[1]), "r"(a[2]), "r"(a[3]), "r"(b0), "r"(b1));
}

// ---------------- kernel 1: u_l = W @ a_l, u_r = W @ a_r ----------------
__global__ void __launch_bounds__(256) u_kernel(const float* __restrict__ W,
                                                const float* __restrict__ b,
                                                const float* __restrict__ a,
                                                const float* __restrict__ ab) {
    __shared__ float sa[2 * OUTD];
    const int tid = threadIdx.x;
    sa[tid]       = a[tid];
    sa[tid + 256] = a[tid + 256];
    __syncthreads();
    const int lane = tid & 31;
    const int k    = blockIdx.x * 8 + (tid >> 5);
    const float* wr = W + (size_t)k * OUTD + lane * 8;
    float4 v0 = *(const float4*)(wr);
    float4 v1 = *(const float4*)(wr + 4);
    const float* s0 = sa + lane * 8;
    const float* s1 = sa + OUTD + lane * 8;
    float ul = v0.x * s0[0] + v0.y * s0[1] + v0.z * s0[2] + v0.w * s0[3]
             + v1.x * s0[4] + v1.y * s0[5] + v1.z * s0[6] + v1.w * s0[7];
    float ur = v0.x * s1[0] + v0.y * s1[1] + v0.z * s1[2] + v0.w * s1[3]
             + v1.x * s1[4] + v1.y * s1[5] + v1.z * s1[6] + v1.w * s1[7];
    #pragma unroll
    for (int o = 16; o > 0; o >>= 1) {
        ul += __shfl_xor_sync(0xffffffffu, ul, o);
        ur += __shfl_xor_sync(0xffffffffu, ur, o);
    }
    if (lane == 0) { g_ul[k] = ul; g_ur[k] = ur; }
    if (blockIdx.x == 0 && tid == 0) {
        float bl = 0.f, br = 0.f;
        for (int n = 0; n < OUTD; ++n) {
            bl += b[n] * sa[n];
            br += b[n] * sa[OUTD + n];
        }
        g_cb[0] = bl + ab[0];
        g_cb[1] = br;
    }
}

// ---------------- kernel 2: per-node factorized exps of el/er ----------------
__global__ void __launch_bounds__(256) eler_kernel(const float* __restrict__ X) {
    __shared__ float sul[IND], sur[IND];
    const int tid = threadIdx.x;
    sul[tid]       = g_ul[tid];
    sul[tid + 256] = g_ul[tid + 256];
    sur[tid]       = g_ur[tid];
    sur[tid + 256] = g_ur[tid + 256];
    __syncthreads();
    const int lane = tid & 31;
    const int w    = tid >> 5;
    const int i    = blockIdx.x * 8 + w;
    const float* xr = X + (size_t)i * IND;
    float dl = 0.f, dr = 0.f;
    #pragma unroll
    for (int q = 0; q < 4; ++q) {
        int c = q * 128 + lane * 4;
        float4 v = *(const float4*)(xr + c);
        dl += v.x * sul[c] + v.y * sul[c + 1] + v.z * sul[c + 2] + v.w * sul[c + 3];
        dr += v.x * sur[c] + v.y * sur[c + 1] + v.z * sur[c + 2] + v.w * sur[c + 3];
    }
    #pragma unroll
    for (int o = 16; o > 0; o >>= 1) {
        dl += __shfl_xor_sync(0xffffffffu, dl, o);
        dr += __shfl_xor_sync(0xffffffffu, dr, o);
    }
    if (lane == 0) {
        float el = dl + g_cb[0];
        float er = dr + g_cb[1];
        float2 ev, fv;
        ev.x = ex2f(el * LOG2E - 3.0f);
        ev.y = ex2f(el * (0.2f * LOG2E) - 3.0f);
        fv.x = ex2f(er * LOG2E - 3.0f);
        fv.y = ex2f(er * (0.2f * LOG2E) - 3.0f);
        g_elx[i] = ev;
        g_erx[i] = fv;
    }
}

// ---------------- kernel 3: h16 = fp16(X @ W + b), row-major ----------------
__global__ void __launch_bounds__(256) gemm1_kernel(const float* __restrict__ X,
                                                    const float* __restrict__ W,
                                                    const float* __restrict__ b) {
    __shared__ __half sX[128 * 72];
    __shared__ __half sW[64 * 136];
    const int tid  = threadIdx.x;
    const int lane = tid & 31;
    const int wid  = tid >> 5;
    const int mblk = blockIdx.x * 128;
    const int nblk = blockIdx.y * 128;
    const int wm   = (wid >> 1) * 32;
    const int wn   = (wid & 1) * 64;

    float acc[2][8][4];
    #pragma unroll
    for (int i = 0; i < 2; ++i)
        #pragma unroll
        for (int j = 0; j < 8; ++j)
            #pragma unroll
            for (int k = 0; k < 4; ++k) acc[i][j][k] = 0.f;

    for (int k0 = 0; k0 < IND; k0 += 64) {
        __syncthreads();
        #pragma unroll
        for (int pass = 0; pass < 8; ++pass) {
            int row = pass * 16 + (tid >> 4);
            int col = (tid & 15) * 4;
            float4 v = *(const float4*)(X + (size_t)(mblk + row) * IND + k0 + col);
            *(__half2*)&sX[row * 72 + col]     = __floats2half2_rn(v.x, v.y);
            *(__half2*)&sX[row * 72 + col + 2] = __floats2half2_rn(v.z, v.w);
        }
        #pragma unroll
        for (int pass = 0; pass < 8; ++pass) {
            int row = pass * 8 + (tid >> 5);
            int col = (tid & 31) * 4;
            float4 v = *(const float4*)(W + (size_t)(k0 + row) * OUTD + nblk + col);
            *(__half2*)&sW[row * 136 + col]     = __floats2half2_rn(v.x, v.y);
            *(__half2*)&sW[row * 136 + col + 2] = __floats2half2_rn(v.z, v.w);
        }
        __syncthreads();
        #pragma unroll
        for (int kk = 0; kk < 4; ++kk) {
            int kb = kk * 16;
            uint32_t A[2][4];
            #pragma unroll
            for (int mf = 0; mf < 2; ++mf)
                ldmA(A[mf], &sX[(wm + mf * 16 + (lane & 15)) * 72 + kb + (lane >> 4) * 8]);
            #pragma unroll
            for (int nf = 0; nf < 4; ++nf) {
                uint32_t B[4];
                ldmBT(B, &sW[(kb + (lane & 15)) * 136 + wn + nf * 16 + (lane >> 4) * 8]);
                #pragma unroll
                for (int mf = 0; mf < 2; ++mf) {
                    mma16816(acc[mf][2 * nf],     A[mf], B[0], B[1]);
                    mma16816(acc[mf][2 * nf + 1], A[mf], B[2], B[3]);
                }
            }
        }
    }
    #pragma unroll
    for (int mf = 0; mf < 2; ++mf) {
        int grow = mblk + wm + mf * 16 + (lane >> 2);
        #pragma unroll
        for (int nf = 0; nf < 8; ++nf) {
            int gcol = nblk + wn + nf * 8 + (lane & 3) * 2;
            float b0 = b[gcol], b1 = b[gcol + 1];
            *(__half2*)&g_h16[(size_t)grow * OUTD + gcol] =
                __floats2half2_rn(acc[mf][nf][0] + b0, acc[mf][nf][1] + b1);
            *(__half2*)&g_h16[(size_t)(grow + 8) * OUTD + gcol] =
                __floats2half2_rn(acc[mf][nf][2] + b0, acc[mf][nf][3] + b1);
        }
    }
}

// ---------------- kernel 4: fused attention — P[t+1] pipelined under MMA[t] ----
__global__ void __launch_bounds__(256, 2) gat_fused_kernel(const int* __restrict__ adj) {
    extern __shared__ __align__(1024) char smem[];

    const int tid  = threadIdx.x;
    const int lane = tid & 31;
    const int wid  = tid >> 5;
    const int s    = blockIdx.x & 1;
    const int rb   = blockIdx.x >> 1;
    const int i0   = rb * BM;
    const int J0   = s * JRANGE;

    const int r  = tid >> 2;           // 0..63 (P row owned by this thread)
    const int cq = tid & 3;            // col quarter
    const int cg = cq << 4;            // 0,16,32,48
    const int* arow = adj + (size_t)(i0 + r) * NN + J0 + cg;

    const float2 ev = g_elx[i0 + r];

    const int wm = (wid >> 2) * 32;    // MMA row group
    const int wn = (wid & 3) * 64;     // MMA col group

    // ---- prologue: adj[0] LDG; cp {H0, er0, er1}; compute P[0] ----
    int4 a[4];
    #pragma unroll
    for (int q = 0; q < 4; ++q) a[q] = __ldcs((const int4*)(arow + 4 * q));

    #pragma unroll
    for (int p = 0; p < 8; ++p) {
        int idx = p * 256 + tid;
        int row = idx >> 5, cb = idx & 31;
        cp16(smem + SH_OFF + row * 512 + SWZ(row, cb),
             g_h16 + (size_t)(J0 + row) * OUTD + cb * 8);
    }
    if (tid < 32) {
        cp16(smem + SER_OFF + tid * 16,       g_erx + J0 + tid * 2);
        cp16(smem + SER_OFF + 512 + tid * 16, g_erx + J0 + BK + tid * 2);
    }
    cp_commit();
    cp_wait0();
    __syncthreads();    // er0 visible to all threads

    float psum = 0.f;
    {
        const float4* se = (const float4*)(smem + SER_OFF);
        uint32_t pk[8];
        #pragma unroll
        for (int kk = 0; kk < 4; ++kk) {
            float4 f0 = se[(cg + 4 * kk) >> 1];
            float4 f1 = se[((cg + 4 * kk) >> 1) + 1];
            int4 av = a[kk];
            float p0 = fmaxf(ev.x * f0.x, ev.y * f0.y);
            float p1 = fmaxf(ev.x * f0.z, ev.y * f0.w);
            float p2 = fmaxf(ev.x * f1.x, ev.y * f1.y);
            float p3 = fmaxf(ev.x * f1.z, ev.y * f1.w);
            p0 = (av.x > 0) ? p0 : 0.f;
            p1 = (av.y > 0) ? p1 : 0.f;
            p2 = (av.z > 0) ? p2 : 0.f;
            p3 = (av.w > 0) ? p3 : 0.f;
            psum += (p0 + p1) + (p2 + p3);
            pk[2 * kk]     = pack2h(p0, p1);
            pk[2 * kk + 1] = pack2h(p2, p3);
        }
        char* pb = smem + SP_OFF + r * 128;
        *(uint4*)(pb + SWZ(r, 2 * cq))     = make_uint4(pk[0], pk[1], pk[2], pk[3]);
        *(uint4*)(pb + SWZ(r, 2 * cq + 1)) = make_uint4(pk[4], pk[5], pk[6], pk[7]);
    }

    float acc[2][8][4];
    #pragma unroll
    for (int i = 0; i < 2; ++i)
        #pragma unroll
        for (int j = 0; j < 8; ++j)
            #pragma unroll
            for (int k = 0; k < 4; ++k) acc[i][j][k] = 0.f;

    // ---- main loop ----
    for (int t = 0; t < NTILES; ++t) {
        cp_wait0();        // {H[t], er[t+1]} landed (group issued at t-1)
        __syncthreads();   // visible to all; P[t] STS visible; MMA[t-1] done

        const bool more = (t + 1 < NTILES);

        // adj[t+1] for P[t+1] (consumed late in kk loop -> latency hidden)
        if (more) {
            const int4* an = (const int4*)(arow + (t + 1) * BK);
            #pragma unroll
            for (int q = 0; q < 4; ++q) a[q] = __ldcs(an + q);
        }

        // issue {H[t+1] -> buf (t+1)&1 (freed by MMA[t-1]), er[t+2] -> (t+2)%3}
        if (more) {
            const int jn = J0 + (t + 1) * BK;
            #pragma unroll
            for (int p = 0; p < 8; ++p) {
                int idx = p * 256 + tid;
                int row = idx >> 5, cb = idx & 31;
                cp16(smem + SH_OFF + ((t + 1) & 1) * SH_BUF + row * 512 + SWZ(row, cb),
                     g_h16 + (size_t)(jn + row) * OUTD + cb * 8);
            }
            if (t + 2 < NTILES && tid < 32)
                cp16(smem + SER_OFF + ((t + 2) % 3) * 512 + tid * 16,
                     g_erx + J0 + (t + 2) * BK + tid * 2);
            cp_commit();
        }

        const char*   sPb = smem + SP_OFF + (t & 1) * SP_BUF;
        const char*   sHb = smem + SH_OFF + (t & 1) * SH_BUF;
        const float4* se  = (const float4*)(smem + SER_OFF + ((t + 1) % 3) * 512);

        uint32_t pk[8];

        #pragma unroll
        for (int kk = 0; kk < 4; ++kk) {
            // MMA[t], k-slab kk
            uint32_t A[2][4];
            #pragma unroll
            for (int mf = 0; mf < 2; ++mf) {
                int prow = wm + mf * 16 + (lane & 15);
                ldmA(A[mf], sPb + prow * 128 + SWZ(prow, kk * 2 + (lane >> 4)));
            }
            const int krow = (kk << 4) + (lane & 15);
            const char* hb = sHb + krow * 512;
            #pragma unroll
            for (int nf = 0; nf < 4; ++nf) {
                uint32_t B[4];
                ldmBT(B, hb + SWZ(krow, (wn >> 3) + nf * 2 + (lane >> 4)));
                mma16816(acc[0][2 * nf],     A[0], B[0], B[1]);
                mma16816(acc[0][2 * nf + 1], A[0], B[2], B[3]);
                mma16816(acc[1][2 * nf],     A[1], B[0], B[1]);
                mma16816(acc[1][2 * nf + 1], A[1], B[2], B[3]);
            }

            // P[t+1], quarter kk (FMA pipe; overlaps LDSM/HMMA above)
            if (more) {
                float4 f0 = se[(cg + 4 * kk) >> 1];
                float4 f1 = se[((cg + 4 * kk) >> 1) + 1];
                int4 av = a[kk];
                float p0 = fmaxf(ev.x * f0.x, ev.y * f0.y);
                float p1 = fmaxf(ev.x * f0.z, ev.y * f0.w);
                float p2 = fmaxf(ev.x * f1.x, ev.y * f1.y);
                float p3 = fmaxf(ev.x * f1.z, ev.y * f1.w);
                p0 = (av.x > 0) ? p0 : 0.f;
                p1 = (av.y > 0) ? p1 : 0.f;
                p2 = (av.z > 0) ? p2 : 0.f;
                p3 = (av.w > 0) ? p3 : 0.f;
                psum += (p0 + p1) + (p2 + p3);
                pk[2 * kk]     = pack2h(p0, p1);
                pk[2 * kk + 1] = pack2h(p2, p3);
            }
        }

        // store P[t+1] into the other sP buffer (read starts after next sync)
        if (more) {
            char* pb = smem + SP_OFF + ((t + 1) & 1) * SP_BUF + r * 128;
            *(uint4*)(pb + SWZ(r, 2 * cq))     = make_uint4(pk[0], pk[1], pk[2], pk[3]);
            *(uint4*)(pb + SWZ(r, 2 * cq + 1)) = make_uint4(pk[4], pk[5], pk[6], pk[7]);
        }
    }

    // rowsum: threads 4r..4r+3 are consecutive lanes
    psum += __shfl_xor_sync(0xffffffffu, psum, 1);
    psum += __shfl_xor_sync(0xffffffffu, psum, 2);
    if ((tid & 3) == 0) g_Lp[s * NN + i0 + r] = psum;

    // write partial numerators
    #pragma unroll
    for (int mf = 0; mf < 2; ++mf) {
        int row0 = wm + mf * 16 + (lane >> 2);
        float* d0 = g_part + ((size_t)s * NN + i0 + row0) * OUTD;
        float* d1 = g_part + ((size_t)s * NN + i0 + row0 + 8) * OUTD;
        #pragma unroll
        for (int nf = 0; nf < 8; ++nf) {
            int col = wn + nf * 8 + (lane & 3) * 2;
            *(float2*)(d0 + col) = make_float2(acc[mf][nf][0], acc[mf][nf][1]);
            *(float2*)(d1 + col) = make_float2(acc[mf][nf][2], acc[mf][nf][3]);
        }
    }
}

// ---------------- kernel 5: combine split-K partials ----------------
__global__ void __launch_bounds__(256) combine_kernel(float* __restrict__ out) {
    const int gid = blockIdx.x * 256 + threadIdx.x;
    const int row = gid >> 6;
    const int c   = (gid & 63) * 4;
    const float4 x0 = *(const float4*)(g_part + (size_t)row * OUTD + c);
    const float4 x1 = *(const float4*)(g_part + (size_t)NN * OUTD + (size_t)row * OUTD + c);
    const float inv = 1.0f / (g_Lp[row] + g_Lp[NN + row]);
    float4 o;
    o.x = (x0.x + x1.x) * inv;
    o.y = (x0.y + x1.y) * inv;
    o.z = (x0.z + x1.z) * inv;
    o.w = (x0.w + x1.w) * inv;
    *(float4*)(out + (size_t)row * OUTD + c) = o;
}

// ---------------- launch ----------------
extern "C" void kernel_launch(void* const* d_in, const int* in_sizes, int n_in,
                              void* d_out, int out_size) {
    const int*   adj = (const int*)d_in[0];
    const float* X   = (const float*)d_in[1];
    const float* W   = (const float*)d_in[2];
    const float* b   = (const float*)d_in[3];
    const float* a   = (const float*)d_in[4];
    const float* ab  = (const float*)d_in[5];
    float* out = (float*)d_out;

    cudaFuncSetAttribute(gat_fused_kernel,
                         cudaFuncAttributeMaxDynamicSharedMemorySize, SMEM_FUSED);

    u_kernel<<<64, 256>>>(W, b, a, ab);
    eler_kernel<<<NN / 8, 256>>>(X);
    gemm1_kernel<<<dim3(NN / 128, OUTD / 128), 256>>>(X, W, b);
    gat_fused_kernel<<<(NN / BM) * SPLITS, 256, SMEM_FUSED>>>(adj);
    combine_kernel<<<(NN * OUTD / 4) / 256, 256>>>(out);
}